// round 15
// baseline (speedup 1.0000x reference)
#include <cuda_runtime.h>
#include <cuda_fp16.h>
#include <math.h>

#define DEVI __device__ __forceinline__

constexpr int FFT_N  = 1 << 19;          // 524288 = 512 x 1024
constexpr int N1     = 512;
constexpr int N2     = 1024;
constexpr int LX     = 960000;
constexpr int KLEN   = 144000;
constexpr int VALID  = FFT_N - KLEN + 1; // 380289
constexpr int NFRAME = 3;
constexpr int NPAIR  = 8;
constexpr int NSIG   = NPAIR * NFRAME;   // 24
constexpr float INV_N = 1.0f / (float)FFT_N;
constexpr float TWO_PI = 6.2831853071795865f;
constexpr float TSCALE = 32768.0f;       // tail pre-scale (fp16-friendly dynamic range)
constexpr float INV_TS = 1.0f / TSCALE;

// Static device scratch (allocation-free, graph-safe). Tail path in fp16.
__device__ __half2 g_A[(size_t)NSIG * FFT_N];
__device__ __half2 g_B[(size_t)NSIG * FFT_N];
__device__ float2 g_hT[FFT_N];
__device__ float2 g_hS[FFT_N];

DEVI float2 cadd(float2 a, float2 b) { return make_float2(a.x + b.x, a.y + b.y); }
DEVI float2 csub(float2 a, float2 b) { return make_float2(a.x - b.x, a.y - b.y); }
DEVI float2 cmul(float2 a, float2 b) {
    return make_float2(a.x * b.x - a.y * b.y, a.x * b.y + a.y * b.x);
}
DEVI __half2 f2h(float2 v) { return __floats2half2_rn(v.x, v.y); }
DEVI float2 h2f(__half2 h) { return __half22float2(h); }

// smem element conversion helpers
DEVI float2 fromS(const float2& v)  { return v; }
DEVI float2 fromS(const __half2& v) { return h2f(v); }
template<typename ST> DEVI ST toS(float2 v);
template<> DEVI float2  toS<float2>(float2 v)  { return v; }
template<> DEVI __half2 toS<__half2>(float2 v) { return f2h(v); }

// twiddle via MUFU: w = exp(SIGN * 2*pi*i * frac)
template<int SIGN>
DEVI float2 wgen(float frac) {
    float sn, cs;
    __sincosf((float)SIGN * TWO_PI * frac, &sn, &cs);
    return make_float2(cs, sn);
}

// Grouped twiddle apply: w^1..w^15 with depth ~8 (4 parallel chains off w^4 bases).
DEVI void twapply16g(float2 v[16], float2 w) {
    float2 w2  = cmul(w, w);
    float2 w4  = cmul(w2, w2);
    float2 w8  = cmul(w4, w4);
    float2 w12 = cmul(w8, w4);
    float2 t0 = w;
    v[1] = cmul(v[1], t0); t0 = cmul(t0, w);
    v[2] = cmul(v[2], t0); t0 = cmul(t0, w);
    v[3] = cmul(v[3], t0);
    float2 t1 = w4;
    v[4] = cmul(v[4], t1); t1 = cmul(t1, w);
    v[5] = cmul(v[5], t1); t1 = cmul(t1, w);
    v[6] = cmul(v[6], t1); t1 = cmul(t1, w);
    v[7] = cmul(v[7], t1);
    float2 t2 = w8;
    v[8]  = cmul(v[8],  t2); t2 = cmul(t2, w);
    v[9]  = cmul(v[9],  t2); t2 = cmul(t2, w);
    v[10] = cmul(v[10], t2); t2 = cmul(t2, w);
    v[11] = cmul(v[11], t2);
    float2 t3 = w12;
    v[12] = cmul(v[12], t3); t3 = cmul(t3, w);
    v[13] = cmul(v[13], t3); t3 = cmul(t3, w);
    v[14] = cmul(v[14], t3); t3 = cmul(t3, w);
    v[15] = cmul(v[15], t3);
}

// Apply geometric twiddle chain w^1..w^7 (H pipeline only).
DEVI void twchain(float2 v[8], float2 w) {
    float2 t = w;
    v[1] = cmul(v[1], t);
#pragma unroll
    for (int j = 2; j < 8; j++) { t = cmul(t, w); v[j] = cmul(v[j], t); }
}

template<int SIGN>
DEVI float2 cmw(float2 v, float wr, float wi) {
    return cmul(v, make_float2(wr, SIGN < 0 ? wi : -wi));
}

// Constant twiddles W32^j (forward values): apply to v[1..15].
template<int SIGN>
DEVI void twconst_W32(float2 v[16]) {
    v[1]  = cmw<SIGN>(v[1],  0.98078528f, -0.19509032f);
    v[2]  = cmw<SIGN>(v[2],  0.92387953f, -0.38268343f);
    v[3]  = cmw<SIGN>(v[3],  0.83146961f, -0.55557023f);
    v[4]  = cmw<SIGN>(v[4],  0.70710678f, -0.70710678f);
    v[5]  = cmw<SIGN>(v[5],  0.55557023f, -0.83146961f);
    v[6]  = cmw<SIGN>(v[6],  0.38268343f, -0.92387953f);
    v[7]  = cmw<SIGN>(v[7],  0.19509032f, -0.98078528f);
    v[8]  = cmw<SIGN>(v[8],  0.0f,        -1.0f);
    v[9]  = cmw<SIGN>(v[9], -0.19509032f, -0.98078528f);
    v[10] = cmw<SIGN>(v[10],-0.38268343f, -0.92387953f);
    v[11] = cmw<SIGN>(v[11],-0.55557023f, -0.83146961f);
    v[12] = cmw<SIGN>(v[12],-0.70710678f, -0.70710678f);
    v[13] = cmw<SIGN>(v[13],-0.83146961f, -0.55557023f);
    v[14] = cmw<SIGN>(v[14],-0.92387953f, -0.38268343f);
    v[15] = cmw<SIGN>(v[15],-0.98078528f, -0.19509032f);
}

// ---------------- 8-point DFT (H pipeline) ----------------
template<int SIGN>
DEVI void fft8(float2 v[8]) {
    const float C1 = 0.70710678118654752f;
    const float S = (float)SIGN;
    float2 y0 = cadd(v[0], v[4]), z0 = csub(v[0], v[4]);
    float2 y1 = cadd(v[1], v[5]), z1 = csub(v[1], v[5]);
    float2 y2 = cadd(v[2], v[6]), z2 = csub(v[2], v[6]);
    float2 y3 = cadd(v[3], v[7]), z3 = csub(v[3], v[7]);
    z1 = make_float2(C1 * (z1.x - S * z1.y), C1 * (S * z1.x + z1.y));
    z2 = make_float2(-S * z2.y, S * z2.x);
    z3 = make_float2(-C1 * (z3.x + S * z3.y), C1 * (S * z3.x - z3.y));
    {
        float2 t0 = cadd(y0, y2), t1 = csub(y0, y2);
        float2 t2 = cadd(y1, y3), t3 = csub(y1, y3);
        float2 it3 = make_float2(-S * t3.y, S * t3.x);
        v[0] = cadd(t0, t2); v[2] = cadd(t1, it3);
        v[4] = csub(t0, t2); v[6] = csub(t1, it3);
    }
    {
        float2 t0 = cadd(z0, z2), t1 = csub(z0, z2);
        float2 t2 = cadd(z1, z3), t3 = csub(z1, z3);
        float2 it3 = make_float2(-S * t3.y, S * t3.x);
        v[1] = cadd(t0, t2); v[3] = cadd(t1, it3);
        v[5] = csub(t0, t2); v[7] = csub(t1, it3);
    }
}

// ---------------- 4-point DFT in registers (in-place on 4 refs) ----------------
template<int SIGN>
DEVI void fft4i(float2& a, float2& b, float2& c, float2& d) {
    const float S = (float)SIGN;
    float2 t0 = cadd(a, c), t1 = csub(a, c);
    float2 t2 = cadd(b, d), t3 = csub(b, d);
    float2 it3 = make_float2(-S * t3.y, S * t3.x);
    a = cadd(t0, t2); b = cadd(t1, it3);
    c = csub(t0, t2); d = csub(t1, it3);
}

// ---------------- 16-point DFT in registers, natural in/out ----------------
template<int SIGN>
DEVI void fft16(float2 v[16]) {
    const float C8  = 0.70710678118654752f;
    const float C16 = 0.92387953251128674f;
    const float S16 = 0.38268343236508977f;
    float2 t[16];
    {
        float2 a = v[0], b = v[4], c = v[8], d = v[12];
        fft4i<SIGN>(a, b, c, d);
        t[0] = a; t[1] = b; t[2] = c; t[3] = d;
    }
    {
        float2 a = v[1], b = v[5], c = v[9], d = v[13];
        fft4i<SIGN>(a, b, c, d);
        t[4] = a;
        t[5] = cmw<SIGN>(b,  C16, -S16);
        t[6] = cmw<SIGN>(c,  C8,  -C8);
        t[7] = cmw<SIGN>(d,  S16, -C16);
    }
    {
        float2 a = v[2], b = v[6], c = v[10], d = v[14];
        fft4i<SIGN>(a, b, c, d);
        t[8]  = a;
        t[9]  = cmw<SIGN>(b,  C8,  -C8);
        t[10] = cmw<SIGN>(c,  0.f, -1.f);
        t[11] = cmw<SIGN>(d, -C8,  -C8);
    }
    {
        float2 a = v[3], b = v[7], c = v[11], d = v[15];
        fft4i<SIGN>(a, b, c, d);
        t[12] = a;
        t[13] = cmw<SIGN>(b,  S16, -C16);
        t[14] = cmw<SIGN>(c, -C8,  -C8);
        t[15] = cmw<SIGN>(d, -C16,  S16);
    }
#pragma unroll
    for (int r = 0; r < 4; r++) {
        float2 a = t[r], b = t[r + 4], c = t[r + 8], d = t[r + 12];
        fft4i<SIGN>(a, b, c, d);
        v[r] = a; v[r + 4] = b; v[r + 8] = c; v[r + 12] = d;
    }
}

// ============ column FFT-512: 16 cols x 512 rows, 512 thr, 16 pts/thread ============
#define CIDX(n1, c) ((n1) * 17 + (c))
constexpr int CSMEM_ELEMS  = 511 * 17 + 15 + 1;                 // 8703
constexpr int CSMEM_B_F32  = CSMEM_ELEMS * 8;                   // 69624 (pass A)
constexpr int CSMEM_B_F16  = CSMEM_ELEMS * 4;                   // 34812 (pass C)

// Stages 0 and 1 only; leaves stage-2 input resident in smem (synced).
template<int SIGN, typename ST>
DEVI void col_fft512_01(float2 v[16], ST* sb, int c, int r) {
    // stage 0: R=16, s=1, p=r; twiddle via MUFU
    fft16<SIGN>(v);
    twapply16g(v, wgen<SIGN>((float)r * (1.0f / 512.0f)));
#pragma unroll
    for (int j = 0; j < 16; j++) sb[CIDX(16 * r + j, c)] = toS<ST>(v[j]);
    __syncthreads();
    // stage 1: R=16, s=16; p = r>>4 in {0,1} warp-uniform; constant twiddles W32^j
#pragma unroll
    for (int j = 0; j < 16; j++) v[j] = fromS(sb[CIDX(r + 32 * j, c)]);
    fft16<SIGN>(v);
    {
        int q = r & 15, p = r >> 4;
        if (p) twconst_W32<SIGN>(v);
        __syncthreads();
#pragma unroll
        for (int j = 0; j < 16; j++) sb[CIDX(q + 256 * p + 16 * j, c)] = toS<ST>(v[j]);
    }
    __syncthreads();
}

// Full column FFT-512 (stage 2 into registers).
template<int SIGN, typename ST>
DEVI void col_fft512(float2 v[16], ST* sb, int c, int r) {
    col_fft512_01<SIGN, ST>(v, sb, c, r);
    // stage 2: R=2, s=256, twiddle-free
#pragma unroll
    for (int m = 0; m < 8; m++) {
        float2 a = fromS(sb[CIDX(r + 32 * m, c)]);
        float2 b = fromS(sb[CIDX(r + 32 * m + 256, c)]);
        v[m]     = cadd(a, b);
        v[m + 8] = csub(a, b);
    }
}

// ---------------- Pass A (fused): main gather-FFT + H build-FFT, fp32 smem -----------------
constexpr int A_MAIN_BLOCKS = NSIG * (N2 / 16);   // 1536
constexpr int A_H_BLOCKS    = N2 / 16;            // 64

__global__ void __launch_bounds__(512, 2) passA_fused(const float* __restrict__ x,
                                                      const float* __restrict__ irp) {
    extern __shared__ __align__(16) char smraw[];
    float2* sb = (float2*)smraw;
    int c = threadIdx.x & 15, r = threadIdx.x >> 4;   // r in [0,32)

    if (blockIdx.x < A_MAIN_BLOCKS) {
        int sig = blockIdx.x >> 6;
        int cb  = (blockIdx.x & 63) << 4;
        int pair = sig / NFRAME;
        int f    = sig - pair * NFRAME;
        const float* x0 = x + (size_t)(2 * pair) * LX;
        const float* x1 = x0 + LX;
        int n2 = cb + c;
        int pos0 = f * VALID - (KLEN - 1) + r * N2 + n2;
        float2 v[16];
#pragma unroll
        for (int m = 0; m < 16; m++) {
            int pos = pos0 + m * (32 * N2);
            float re = 0.f, im = 0.f;
            if (pos >= 0 && pos < LX) { re = __ldg(x0 + pos); im = __ldg(x1 + pos); }
            v[m] = make_float2(re, im);
        }
        col_fft512<-1, float2>(v, sb, c, r);

        float sn, cs;
        __sincosf(-TWO_PI * (float)(n2 * r) * INV_N, &sn, &cs);
        float2 base = make_float2(cs, sn);
        __sincosf(-TWO_PI * (float)n2 * (1.0f / 16384.0f), &sn, &cs);
        float2 stp = make_float2(cs, sn);
        float2 stp2 = cmul(stp, stp);
        float2 stp4 = cmul(stp2, stp2);
        float2 b0 = base;
        float2 b1 = cmul(b0, stp4);
        float2 b2 = cmul(b1, stp4);
        float2 b3 = cmul(b2, stp4);

        __half2* out = g_A + (size_t)sig * FFT_N;
#pragma unroll
        for (int e = 0; e < 4; e++) {
            out[(r + 32 * (e))      * N2 + n2] = f2h(cmul(v[e],      b0));
            out[(r + 32 * (e + 4))  * N2 + n2] = f2h(cmul(v[e + 4],  b1));
            out[(r + 32 * (e + 8))  * N2 + n2] = f2h(cmul(v[e + 8],  b2));
            out[(r + 32 * (e + 12)) * N2 + n2] = f2h(cmul(v[e + 12], b3));
            if (e < 3) {
                b0 = cmul(b0, stp); b1 = cmul(b1, stp);
                b2 = cmul(b2, stp); b3 = cmul(b3, stp);
            }
        }
    } else {
        // H path: tail-only taps (identity split out), scaled TSCALE/N
        int cb = (blockIdx.x - A_MAIN_BLOCKS) << 4;
        int n2 = cb + c;
        const float hsc = INV_N * TSCALE;
        float2 v[16];
#pragma unroll
        for (int m = 0; m < 16; m++) {
            int n = (r + 32 * m) * N2 + n2;
            float hv = 0.f;
            if (n >= 1 && n < KLEN) hv = tanhf(__ldg(irp + KLEN - 1 - n));
            v[m] = make_float2(hv * hsc, 0.f);
        }
        col_fft512<-1, float2>(v, sb, c, r);

        float sn, cs;
        __sincosf(-TWO_PI * (float)(n2 * r) * INV_N, &sn, &cs);
        float2 cw = make_float2(cs, sn);
        __sincosf(-TWO_PI * (float)n2 * (1.0f / 16384.0f), &sn, &cs);
        float2 stp = make_float2(cs, sn);
#pragma unroll
        for (int m = 0; m < 16; m++) {
            g_hT[(r + 32 * m) * N2 + n2] = cmul(v[m], cw);
            cw = cmul(cw, stp);
        }
    }
}

// padded smem index: +2 per 16
#define PD(i) ((i) + ((((i) >> 4)) << 1))

// ---------------- Pass B (H): forward row FFT-1024 (2.8.8.8), fp32 ----------
__global__ void __launch_bounds__(128) passB_H() {
    __shared__ __align__(16) float2 sb[2][1152];
    int k1 = blockIdx.x;
    const float2* rin = g_hT + (size_t)k1 * N2;
    int t = threadIdx.x;
    float2 v[8];
#pragma unroll
    for (int j = 0; j < 8; j++) v[j] = __ldg(rin + t + 128 * j);
#pragma unroll
    for (int m = 0; m < 4; m++) {
        int p = t + 128 * m;
        float2 e = cadd(v[m], v[m + 4]);
        float2 o = cmul(wgen<-1>((float)p * (1.0f / 1024.0f)), csub(v[m], v[m + 4]));
        *(float4*)&sb[0][PD(2 * p)] = make_float4(e.x, e.y, o.x, o.y);
    }
    __syncthreads();
#pragma unroll
    for (int j = 0; j < 8; j++) v[j] = sb[0][PD(t + 128 * j)];
    fft8<-1>(v);
    {
        int q = t & 1, p = t >> 1;
        twchain(v, wgen<-1>((float)(2 * p) * (1.0f / 1024.0f)));
#pragma unroll
        for (int j = 0; j < 8; j++) sb[1][PD(q + 16 * p + 2 * j)] = v[j];
    }
    __syncthreads();
#pragma unroll
    for (int j = 0; j < 8; j++) v[j] = sb[1][PD(t + 128 * j)];
    fft8<-1>(v);
    {
        int q = t & 15, p = t >> 4;
        twchain(v, wgen<-1>((float)(16 * p) * (1.0f / 1024.0f)));
#pragma unroll
        for (int j = 0; j < 8; j++) sb[0][PD(q + 128 * p + 16 * j)] = v[j];
    }
    __syncthreads();
#pragma unroll
    for (int j = 0; j < 8; j++) v[j] = sb[0][PD(t + 128 * j)];
    fft8<-1>(v);
#pragma unroll
    for (int j = 0; j < 8; j++) g_hS[(size_t)k1 * N2 + t + 128 * j] = v[j];
}

// ---------------- Pass B (main): FFT-1024 x H x iFFT, fp16 smem, 2 rows/block (R12) -------
__global__ void __launch_bounds__(128, 8) passB_main() {
    __shared__ __align__(16) __half2 sb[2][1152];
    int lr = threadIdx.x >> 6;
    int t  = threadIdx.x & 63;
    int row = blockIdx.x * 2 + lr;
    int sig = row >> 9, k1 = row & 511;
    const __half2* rin  = g_A + (size_t)sig * FFT_N + (size_t)k1 * N2;
    const float2*  hrow = g_hS + (size_t)k1 * N2;
    __half2*       rout = g_B + (size_t)sig * FFT_N + (size_t)k1 * N2;
    __half2* S = sb[lr];

    float2 v[16];
#pragma unroll
    for (int m = 0; m < 16; m++) v[m] = h2f(__ldg(rin + t + 64 * m));
    fft16<-1>(v);
    twapply16g(v, wgen<-1>((float)t * (1.0f / 1024.0f)));
#pragma unroll
    for (int m = 0; m < 8; m++) {
        __half2 h0 = f2h(v[2 * m]), h1 = f2h(v[2 * m + 1]);
        *(uint2*)&S[18 * t + 2 * m] = make_uint2(*(unsigned*)&h0, *(unsigned*)&h1);
    }
    __syncthreads();

#pragma unroll
    for (int m = 0; m < 16; m++) v[m] = h2f(S[PD(t + 64 * m)]);
    fft16<-1>(v);
    {
        int q = t & 15, p = t >> 4;
        twapply16g(v, wgen<-1>((float)p * (1.0f / 64.0f)));
        __syncthreads();
#pragma unroll
        for (int m = 0; m < 16; m++) S[PD(q + 256 * p + 16 * m)] = f2h(v[m]);
    }
    __syncthreads();

    float2 s16[16];
#pragma unroll
    for (int i = 0; i < 4; i++) {
        float2 a = h2f(S[PD(t + 64 * i)]);
        float2 b = h2f(S[PD(t + 64 * i + 256)]);
        float2 c = h2f(S[PD(t + 64 * i + 512)]);
        float2 d = h2f(S[PD(t + 64 * i + 768)]);
        fft4i<-1>(a, b, c, d);
        s16[i] = a; s16[i + 4] = b; s16[i + 8] = c; s16[i + 12] = d;
    }

#pragma unroll
    for (int m = 0; m < 16; m++) s16[m] = cmul(s16[m], __ldg(hrow + t + 64 * m));

    fft16<1>(s16);
    twapply16g(s16, wgen<1>((float)t * (1.0f / 1024.0f)));
    __syncthreads();
#pragma unroll
    for (int m = 0; m < 8; m++) {
        __half2 h0 = f2h(s16[2 * m]), h1 = f2h(s16[2 * m + 1]);
        *(uint2*)&S[18 * t + 2 * m] = make_uint2(*(unsigned*)&h0, *(unsigned*)&h1);
    }
    __syncthreads();

#pragma unroll
    for (int m = 0; m < 16; m++) v[m] = h2f(S[PD(t + 64 * m)]);
    fft16<1>(v);
    {
        int q = t & 15, p = t >> 4;
        twapply16g(v, wgen<1>((float)p * (1.0f / 64.0f)));
        __syncthreads();
#pragma unroll
        for (int m = 0; m < 16; m++) S[PD(q + 256 * p + 16 * m)] = f2h(v[m]);
    }
    __syncthreads();

    float sn, cs;
    __sincosf(TWO_PI * (float)(k1 * t) * INV_N, &sn, &cs);
    float2 base = make_float2(cs, sn);
    __sincosf(TWO_PI * (float)k1 * (1.0f / 8192.0f), &sn, &cs);
    float2 A = make_float2(cs, sn);
    __sincosf(TWO_PI * (float)k1 * (1.0f / 2048.0f), &sn, &cs);
    float2 Bm = make_float2(cs, sn);
    float2 ob[4];
    ob[0] = base;
    ob[1] = cmul(base, A);
    ob[2] = cmul(ob[1], A);
    ob[3] = cmul(ob[2], A);
#pragma unroll
    for (int i = 0; i < 4; i++) {
        float2 a = h2f(S[PD(t + 64 * i)]);
        float2 b = h2f(S[PD(t + 64 * i + 256)]);
        float2 c = h2f(S[PD(t + 64 * i + 512)]);
        float2 d = h2f(S[PD(t + 64 * i + 768)]);
        fft4i<1>(a, b, c, d);
        float2 w = ob[i];
        rout[t + 64 * i]       = f2h(cmul(a, w)); w = cmul(w, Bm);
        rout[t + 64 * i + 256] = f2h(cmul(b, w)); w = cmul(w, Bm);
        rout[t + 64 * i + 512] = f2h(cmul(c, w)); w = cmul(w, Bm);
        rout[t + 64 * i + 768] = f2h(cmul(d, w));
    }
}

// ---------------- Pass C: column iFFT-512 (fp16 smem), stage-2 fused with x-add/store ------
__global__ void __launch_bounds__(512, 2) passC(float* __restrict__ dout,
                                                const float* __restrict__ x) {
    extern __shared__ __align__(16) char smraw[];
    __half2* sb = (__half2*)smraw;
    int sig = blockIdx.x >> 6;
    int cb  = (blockIdx.x & 63) << 4;
    int pair = sig / NFRAME;
    int f    = sig - pair * NFRAME;
    const __half2* in = g_B + (size_t)sig * FFT_N;

    int c = threadIdx.x & 15, r = threadIdx.x >> 4;
    int n2 = cb + c;
    float2 v[16];
#pragma unroll
    for (int m = 0; m < 16; m++) v[m] = h2f(__ldg(in + (r + 32 * m) * N2 + n2));
    col_fft512_01<1, __half2>(v, sb, c, r);   // stage-2 input left in smem

    int b0 = 2 * pair;
    const float* x0 = x + (size_t)b0 * LX;
    const float* x1 = x0 + LX;
    float* o0 = dout + (size_t)b0 * LX;
    float* o1 = o0 + LX;
    int base = f * VALID - (KLEN - 1) + r * N2 + n2;   // tt for m=0 plus f*VALID folded

    // stage 2 (radix-2, twiddle-free) fused with identity add + overlap-save scatter.
    // Upper output n1+256: tt >= 256*1024 - 143999 > 0 always (no low-bound check needed).
#pragma unroll
    for (int m = 0; m < 8; m++) {
        float2 a = h2f(sb[CIDX(r + 32 * m, c)]);
        float2 b = h2f(sb[CIDX(r + 32 * m + 256, c)]);
        float2 s = cadd(a, b);
        float2 d = csub(a, b);
        int noa = base + m * (32 * N2);                // = f*VALID + tt(n1a)
        if (noa >= f * VALID && noa < LX) {            // tt >= 0 && no < LX
            o0[noa] = fmaf(s.x, INV_TS, __ldg(x0 + noa));
            o1[noa] = fmaf(s.y, INV_TS, __ldg(x1 + noa));
        }
        int nob = noa + 256 * N2;
        if (nob < LX) {
            o0[nob] = fmaf(d.x, INV_TS, __ldg(x0 + nob));
            o1[nob] = fmaf(d.y, INV_TS, __ldg(x1 + nob));
        }
    }
}

extern "C" void kernel_launch(void* const* d_in, const int* in_sizes, int n_in,
                              void* d_out, int out_size) {
    (void)in_sizes; (void)n_in; (void)out_size;
    const float* x   = (const float*)d_in[0];
    const float* irp = (const float*)d_in[1];
    float* out = (float*)d_out;

    cudaFuncSetAttribute(passA_fused, cudaFuncAttributeMaxDynamicSharedMemorySize, CSMEM_B_F32);

    passA_fused<<<A_MAIN_BLOCKS + A_H_BLOCKS, 512, CSMEM_B_F32>>>(x, irp);  // 1600 blocks
    passB_H<<<N1, 128>>>();                                                  // 512 blocks
    passB_main<<<NSIG * N1 / 2, 128>>>();                                    // 6144 blocks
    passC<<<NSIG * (N2 / 16), 512, CSMEM_B_F16>>>(out, x);                   // 1536 blocks
}

// round 16
// speedup vs baseline: 1.0161x; 1.0161x over previous
#include <cuda_runtime.h>
#include <cuda_fp16.h>
#include <math.h>

#define DEVI __device__ __forceinline__

constexpr int FFT_N  = 1 << 19;          // 524288 = 512 x 1024
constexpr int N1     = 512;
constexpr int N2     = 1024;
constexpr int LX     = 960000;
constexpr int KLEN   = 144000;
constexpr int VALID  = FFT_N - KLEN + 1; // 380289
constexpr int NFRAME = 3;
constexpr int NPAIR  = 8;
constexpr int NSIG   = NPAIR * NFRAME;   // 24
constexpr float INV_N = 1.0f / (float)FFT_N;
constexpr float TWO_PI = 6.2831853071795865f;
constexpr float TSCALE = 32768.0f;       // tail pre-scale (fp16-friendly dynamic range)
constexpr float INV_TS = 1.0f / TSCALE;

// Static device scratch (allocation-free, graph-safe). Tail path in fp16.
__device__ __half2 g_A[(size_t)NSIG * FFT_N];
__device__ __half2 g_B[(size_t)NSIG * FFT_N];
__device__ float2  g_hT[FFT_N];
__device__ __half2 g_hS[FFT_N];          // H row spectrum, fp16 (read 24x -> halves L2 stream)

DEVI float2 cadd(float2 a, float2 b) { return make_float2(a.x + b.x, a.y + b.y); }
DEVI float2 csub(float2 a, float2 b) { return make_float2(a.x - b.x, a.y - b.y); }
DEVI float2 cmul(float2 a, float2 b) {
    return make_float2(a.x * b.x - a.y * b.y, a.x * b.y + a.y * b.x);
}
DEVI __half2 f2h(float2 v) { return __floats2half2_rn(v.x, v.y); }
DEVI float2 h2f(__half2 h) { return __half22float2(h); }

// smem element conversion helpers
DEVI float2 fromS(const float2& v)  { return v; }
DEVI float2 fromS(const __half2& v) { return h2f(v); }
template<typename ST> DEVI ST toS(float2 v);
template<> DEVI float2  toS<float2>(float2 v)  { return v; }
template<> DEVI __half2 toS<__half2>(float2 v) { return f2h(v); }

// twiddle via MUFU: w = exp(SIGN * 2*pi*i * frac)
template<int SIGN>
DEVI float2 wgen(float frac) {
    float sn, cs;
    __sincosf((float)SIGN * TWO_PI * frac, &sn, &cs);
    return make_float2(cs, sn);
}

// Grouped twiddle apply: w^1..w^15 with depth ~8 (4 parallel chains off w^4 bases).
DEVI void twapply16g(float2 v[16], float2 w) {
    float2 w2  = cmul(w, w);
    float2 w4  = cmul(w2, w2);
    float2 w8  = cmul(w4, w4);
    float2 w12 = cmul(w8, w4);
    float2 t0 = w;
    v[1] = cmul(v[1], t0); t0 = cmul(t0, w);
    v[2] = cmul(v[2], t0); t0 = cmul(t0, w);
    v[3] = cmul(v[3], t0);
    float2 t1 = w4;
    v[4] = cmul(v[4], t1); t1 = cmul(t1, w);
    v[5] = cmul(v[5], t1); t1 = cmul(t1, w);
    v[6] = cmul(v[6], t1); t1 = cmul(t1, w);
    v[7] = cmul(v[7], t1);
    float2 t2 = w8;
    v[8]  = cmul(v[8],  t2); t2 = cmul(t2, w);
    v[9]  = cmul(v[9],  t2); t2 = cmul(t2, w);
    v[10] = cmul(v[10], t2); t2 = cmul(t2, w);
    v[11] = cmul(v[11], t2);
    float2 t3 = w12;
    v[12] = cmul(v[12], t3); t3 = cmul(t3, w);
    v[13] = cmul(v[13], t3); t3 = cmul(t3, w);
    v[14] = cmul(v[14], t3); t3 = cmul(t3, w);
    v[15] = cmul(v[15], t3);
}

// Apply geometric twiddle chain w^1..w^7 (H pipeline only).
DEVI void twchain(float2 v[8], float2 w) {
    float2 t = w;
    v[1] = cmul(v[1], t);
#pragma unroll
    for (int j = 2; j < 8; j++) { t = cmul(t, w); v[j] = cmul(v[j], t); }
}

template<int SIGN>
DEVI float2 cmw(float2 v, float wr, float wi) {
    return cmul(v, make_float2(wr, SIGN < 0 ? wi : -wi));
}

// Constant twiddles W32^j (forward values): apply to v[1..15].
template<int SIGN>
DEVI void twconst_W32(float2 v[16]) {
    v[1]  = cmw<SIGN>(v[1],  0.98078528f, -0.19509032f);
    v[2]  = cmw<SIGN>(v[2],  0.92387953f, -0.38268343f);
    v[3]  = cmw<SIGN>(v[3],  0.83146961f, -0.55557023f);
    v[4]  = cmw<SIGN>(v[4],  0.70710678f, -0.70710678f);
    v[5]  = cmw<SIGN>(v[5],  0.55557023f, -0.83146961f);
    v[6]  = cmw<SIGN>(v[6],  0.38268343f, -0.92387953f);
    v[7]  = cmw<SIGN>(v[7],  0.19509032f, -0.98078528f);
    v[8]  = cmw<SIGN>(v[8],  0.0f,        -1.0f);
    v[9]  = cmw<SIGN>(v[9], -0.19509032f, -0.98078528f);
    v[10] = cmw<SIGN>(v[10],-0.38268343f, -0.92387953f);
    v[11] = cmw<SIGN>(v[11],-0.55557023f, -0.83146961f);
    v[12] = cmw<SIGN>(v[12],-0.70710678f, -0.70710678f);
    v[13] = cmw<SIGN>(v[13],-0.83146961f, -0.55557023f);
    v[14] = cmw<SIGN>(v[14],-0.92387953f, -0.38268343f);
    v[15] = cmw<SIGN>(v[15],-0.98078528f, -0.19509032f);
}

// ---------------- 8-point DFT (H pipeline) ----------------
template<int SIGN>
DEVI void fft8(float2 v[8]) {
    const float C1 = 0.70710678118654752f;
    const float S = (float)SIGN;
    float2 y0 = cadd(v[0], v[4]), z0 = csub(v[0], v[4]);
    float2 y1 = cadd(v[1], v[5]), z1 = csub(v[1], v[5]);
    float2 y2 = cadd(v[2], v[6]), z2 = csub(v[2], v[6]);
    float2 y3 = cadd(v[3], v[7]), z3 = csub(v[3], v[7]);
    z1 = make_float2(C1 * (z1.x - S * z1.y), C1 * (S * z1.x + z1.y));
    z2 = make_float2(-S * z2.y, S * z2.x);
    z3 = make_float2(-C1 * (z3.x + S * z3.y), C1 * (S * z3.x - z3.y));
    {
        float2 t0 = cadd(y0, y2), t1 = csub(y0, y2);
        float2 t2 = cadd(y1, y3), t3 = csub(y1, y3);
        float2 it3 = make_float2(-S * t3.y, S * t3.x);
        v[0] = cadd(t0, t2); v[2] = cadd(t1, it3);
        v[4] = csub(t0, t2); v[6] = csub(t1, it3);
    }
    {
        float2 t0 = cadd(z0, z2), t1 = csub(z0, z2);
        float2 t2 = cadd(z1, z3), t3 = csub(z1, z3);
        float2 it3 = make_float2(-S * t3.y, S * t3.x);
        v[1] = cadd(t0, t2); v[3] = cadd(t1, it3);
        v[5] = csub(t0, t2); v[7] = csub(t1, it3);
    }
}

// ---------------- 4-point DFT in registers (in-place on 4 refs) ----------------
template<int SIGN>
DEVI void fft4i(float2& a, float2& b, float2& c, float2& d) {
    const float S = (float)SIGN;
    float2 t0 = cadd(a, c), t1 = csub(a, c);
    float2 t2 = cadd(b, d), t3 = csub(b, d);
    float2 it3 = make_float2(-S * t3.y, S * t3.x);
    a = cadd(t0, t2); b = cadd(t1, it3);
    c = csub(t0, t2); d = csub(t1, it3);
}

// ---------------- 16-point DFT in registers, natural in/out ----------------
template<int SIGN>
DEVI void fft16(float2 v[16]) {
    const float C8  = 0.70710678118654752f;
    const float C16 = 0.92387953251128674f;
    const float S16 = 0.38268343236508977f;
    float2 t[16];
    {
        float2 a = v[0], b = v[4], c = v[8], d = v[12];
        fft4i<SIGN>(a, b, c, d);
        t[0] = a; t[1] = b; t[2] = c; t[3] = d;
    }
    {
        float2 a = v[1], b = v[5], c = v[9], d = v[13];
        fft4i<SIGN>(a, b, c, d);
        t[4] = a;
        t[5] = cmw<SIGN>(b,  C16, -S16);
        t[6] = cmw<SIGN>(c,  C8,  -C8);
        t[7] = cmw<SIGN>(d,  S16, -C16);
    }
    {
        float2 a = v[2], b = v[6], c = v[10], d = v[14];
        fft4i<SIGN>(a, b, c, d);
        t[8]  = a;
        t[9]  = cmw<SIGN>(b,  C8,  -C8);
        t[10] = cmw<SIGN>(c,  0.f, -1.f);
        t[11] = cmw<SIGN>(d, -C8,  -C8);
    }
    {
        float2 a = v[3], b = v[7], c = v[11], d = v[15];
        fft4i<SIGN>(a, b, c, d);
        t[12] = a;
        t[13] = cmw<SIGN>(b,  S16, -C16);
        t[14] = cmw<SIGN>(c, -C8,  -C8);
        t[15] = cmw<SIGN>(d, -C16,  S16);
    }
#pragma unroll
    for (int r = 0; r < 4; r++) {
        float2 a = t[r], b = t[r + 4], c = t[r + 8], d = t[r + 12];
        fft4i<SIGN>(a, b, c, d);
        v[r] = a; v[r + 4] = b; v[r + 8] = c; v[r + 12] = d;
    }
}

// ============ column FFT-512: 16 cols x 512 rows, 512 thr, 16 pts/thread ============
#define CIDX(n1, c) ((n1) * 17 + (c))
constexpr int CSMEM_ELEMS  = 511 * 17 + 15 + 1;                 // 8703
constexpr int CSMEM_B_F32  = CSMEM_ELEMS * 8;                   // 69624 (pass A)
constexpr int CSMEM_B_F16  = CSMEM_ELEMS * 4;                   // 34812 (pass C)

template<int SIGN, typename ST>
DEVI void col_fft512(float2 v[16], ST* sb, int c, int r) {
    // stage 0: R=16, s=1, p=r; twiddle via MUFU
    fft16<SIGN>(v);
    twapply16g(v, wgen<SIGN>((float)r * (1.0f / 512.0f)));
#pragma unroll
    for (int j = 0; j < 16; j++) sb[CIDX(16 * r + j, c)] = toS<ST>(v[j]);
    __syncthreads();
    // stage 1: R=16, s=16; p = r>>4 in {0,1} warp-uniform; constant twiddles W32^j
#pragma unroll
    for (int j = 0; j < 16; j++) v[j] = fromS(sb[CIDX(r + 32 * j, c)]);
    fft16<SIGN>(v);
    {
        int q = r & 15, p = r >> 4;
        if (p) twconst_W32<SIGN>(v);
        __syncthreads();
#pragma unroll
        for (int j = 0; j < 16; j++) sb[CIDX(q + 256 * p + 16 * j, c)] = toS<ST>(v[j]);
    }
    __syncthreads();
    // stage 2: R=2, s=256, twiddle-free
#pragma unroll
    for (int m = 0; m < 8; m++) {
        float2 a = fromS(sb[CIDX(r + 32 * m, c)]);
        float2 b = fromS(sb[CIDX(r + 32 * m + 256, c)]);
        v[m]     = cadd(a, b);
        v[m + 8] = csub(a, b);
    }
}

// ---------------- Pass A (fused): main gather-FFT + H build-FFT, fp32 smem -----------------
constexpr int A_MAIN_BLOCKS = NSIG * (N2 / 16);   // 1536
constexpr int A_H_BLOCKS    = N2 / 16;            // 64

__global__ void __launch_bounds__(512, 2) passA_fused(const float* __restrict__ x,
                                                      const float* __restrict__ irp) {
    extern __shared__ __align__(16) char smraw[];
    float2* sb = (float2*)smraw;
    int c = threadIdx.x & 15, r = threadIdx.x >> 4;   // r in [0,32)

    if (blockIdx.x < A_MAIN_BLOCKS) {
        int sig = blockIdx.x >> 6;
        int cb  = (blockIdx.x & 63) << 4;
        int pair = sig / NFRAME;
        int f    = sig - pair * NFRAME;
        const float* x0 = x + (size_t)(2 * pair) * LX;
        const float* x1 = x0 + LX;
        int n2 = cb + c;
        int pos0 = f * VALID - (KLEN - 1) + r * N2 + n2;
        float2 v[16];
#pragma unroll
        for (int m = 0; m < 16; m++) {
            int pos = pos0 + m * (32 * N2);
            float re = 0.f, im = 0.f;
            if (pos >= 0 && pos < LX) { re = __ldg(x0 + pos); im = __ldg(x1 + pos); }
            v[m] = make_float2(re, im);
        }
        col_fft512<-1, float2>(v, sb, c, r);

        float sn, cs;
        __sincosf(-TWO_PI * (float)(n2 * r) * INV_N, &sn, &cs);
        float2 base = make_float2(cs, sn);
        __sincosf(-TWO_PI * (float)n2 * (1.0f / 16384.0f), &sn, &cs);
        float2 stp = make_float2(cs, sn);
        float2 stp2 = cmul(stp, stp);
        float2 stp4 = cmul(stp2, stp2);
        float2 b0 = base;
        float2 b1 = cmul(b0, stp4);
        float2 b2 = cmul(b1, stp4);
        float2 b3 = cmul(b2, stp4);

        __half2* out = g_A + (size_t)sig * FFT_N;
#pragma unroll
        for (int e = 0; e < 4; e++) {
            out[(r + 32 * (e))      * N2 + n2] = f2h(cmul(v[e],      b0));
            out[(r + 32 * (e + 4))  * N2 + n2] = f2h(cmul(v[e + 4],  b1));
            out[(r + 32 * (e + 8))  * N2 + n2] = f2h(cmul(v[e + 8],  b2));
            out[(r + 32 * (e + 12)) * N2 + n2] = f2h(cmul(v[e + 12], b3));
            if (e < 3) {
                b0 = cmul(b0, stp); b1 = cmul(b1, stp);
                b2 = cmul(b2, stp); b3 = cmul(b3, stp);
            }
        }
    } else {
        // H path: tail-only taps (identity split out), scaled TSCALE/N
        int cb = (blockIdx.x - A_MAIN_BLOCKS) << 4;
        int n2 = cb + c;
        const float hsc = INV_N * TSCALE;
        float2 v[16];
#pragma unroll
        for (int m = 0; m < 16; m++) {
            int n = (r + 32 * m) * N2 + n2;
            float hv = 0.f;
            if (n >= 1 && n < KLEN) hv = tanhf(__ldg(irp + KLEN - 1 - n));
            v[m] = make_float2(hv * hsc, 0.f);
        }
        col_fft512<-1, float2>(v, sb, c, r);

        float sn, cs;
        __sincosf(-TWO_PI * (float)(n2 * r) * INV_N, &sn, &cs);
        float2 cw = make_float2(cs, sn);
        __sincosf(-TWO_PI * (float)n2 * (1.0f / 16384.0f), &sn, &cs);
        float2 stp = make_float2(cs, sn);
#pragma unroll
        for (int m = 0; m < 16; m++) {
            g_hT[(r + 32 * m) * N2 + n2] = cmul(v[m], cw);
            cw = cmul(cw, stp);
        }
    }
}

// padded smem index: +2 per 16
#define PD(i) ((i) + ((((i) >> 4)) << 1))

// ---------------- Pass B (H): forward row FFT-1024 (2.8.8.8), fp32 compute, fp16 out ------
__global__ void __launch_bounds__(128) passB_H() {
    __shared__ __align__(16) float2 sb[2][1152];
    int k1 = blockIdx.x;
    const float2* rin = g_hT + (size_t)k1 * N2;
    int t = threadIdx.x;
    float2 v[8];
#pragma unroll
    for (int j = 0; j < 8; j++) v[j] = __ldg(rin + t + 128 * j);
#pragma unroll
    for (int m = 0; m < 4; m++) {
        int p = t + 128 * m;
        float2 e = cadd(v[m], v[m + 4]);
        float2 o = cmul(wgen<-1>((float)p * (1.0f / 1024.0f)), csub(v[m], v[m + 4]));
        *(float4*)&sb[0][PD(2 * p)] = make_float4(e.x, e.y, o.x, o.y);
    }
    __syncthreads();
#pragma unroll
    for (int j = 0; j < 8; j++) v[j] = sb[0][PD(t + 128 * j)];
    fft8<-1>(v);
    {
        int q = t & 1, p = t >> 1;
        twchain(v, wgen<-1>((float)(2 * p) * (1.0f / 1024.0f)));
#pragma unroll
        for (int j = 0; j < 8; j++) sb[1][PD(q + 16 * p + 2 * j)] = v[j];
    }
    __syncthreads();
#pragma unroll
    for (int j = 0; j < 8; j++) v[j] = sb[1][PD(t + 128 * j)];
    fft8<-1>(v);
    {
        int q = t & 15, p = t >> 4;
        twchain(v, wgen<-1>((float)(16 * p) * (1.0f / 1024.0f)));
#pragma unroll
        for (int j = 0; j < 8; j++) sb[0][PD(q + 128 * p + 16 * j)] = v[j];
    }
    __syncthreads();
#pragma unroll
    for (int j = 0; j < 8; j++) v[j] = sb[0][PD(t + 128 * j)];
    fft8<-1>(v);
#pragma unroll
    for (int j = 0; j < 8; j++) g_hS[(size_t)k1 * N2 + t + 128 * j] = f2h(v[j]);
}

// ---------------- Pass B (main): FFT-1024 x H x iFFT, fp16 smem, 2 rows/block -------------
__global__ void __launch_bounds__(128, 8) passB_main() {
    __shared__ __align__(16) __half2 sb[2][1152];
    int lr = threadIdx.x >> 6;
    int t  = threadIdx.x & 63;
    int row = blockIdx.x * 2 + lr;
    int sig = row >> 9, k1 = row & 511;
    const __half2* rin  = g_A + (size_t)sig * FFT_N + (size_t)k1 * N2;
    const __half2* hrow = g_hS + (size_t)k1 * N2;
    __half2*       rout = g_B + (size_t)sig * FFT_N + (size_t)k1 * N2;
    __half2* S = sb[lr];

    float2 v[16];
#pragma unroll
    for (int m = 0; m < 16; m++) v[m] = h2f(__ldg(rin + t + 64 * m));
    fft16<-1>(v);
    twapply16g(v, wgen<-1>((float)t * (1.0f / 1024.0f)));
#pragma unroll
    for (int m = 0; m < 8; m++) {
        __half2 h0 = f2h(v[2 * m]), h1 = f2h(v[2 * m + 1]);
        *(uint2*)&S[18 * t + 2 * m] = make_uint2(*(unsigned*)&h0, *(unsigned*)&h1);
    }
    __syncthreads();

#pragma unroll
    for (int m = 0; m < 16; m++) v[m] = h2f(S[PD(t + 64 * m)]);
    fft16<-1>(v);
    {
        int q = t & 15, p = t >> 4;
        twapply16g(v, wgen<-1>((float)p * (1.0f / 64.0f)));
        __syncthreads();
#pragma unroll
        for (int m = 0; m < 16; m++) S[PD(q + 256 * p + 16 * m)] = f2h(v[m]);
    }
    __syncthreads();

    float2 s16[16];
#pragma unroll
    for (int i = 0; i < 4; i++) {
        float2 a = h2f(S[PD(t + 64 * i)]);
        float2 b = h2f(S[PD(t + 64 * i + 256)]);
        float2 c = h2f(S[PD(t + 64 * i + 512)]);
        float2 d = h2f(S[PD(t + 64 * i + 768)]);
        fft4i<-1>(a, b, c, d);
        s16[i] = a; s16[i + 4] = b; s16[i + 8] = c; s16[i + 12] = d;
    }

#pragma unroll
    for (int m = 0; m < 16; m++) s16[m] = cmul(s16[m], h2f(__ldg(hrow + t + 64 * m)));

    fft16<1>(s16);
    twapply16g(s16, wgen<1>((float)t * (1.0f / 1024.0f)));
    __syncthreads();
#pragma unroll
    for (int m = 0; m < 8; m++) {
        __half2 h0 = f2h(s16[2 * m]), h1 = f2h(s16[2 * m + 1]);
        *(uint2*)&S[18 * t + 2 * m] = make_uint2(*(unsigned*)&h0, *(unsigned*)&h1);
    }
    __syncthreads();

#pragma unroll
    for (int m = 0; m < 16; m++) v[m] = h2f(S[PD(t + 64 * m)]);
    fft16<1>(v);
    {
        int q = t & 15, p = t >> 4;
        twapply16g(v, wgen<1>((float)p * (1.0f / 64.0f)));
        __syncthreads();
#pragma unroll
        for (int m = 0; m < 16; m++) S[PD(q + 256 * p + 16 * m)] = f2h(v[m]);
    }
    __syncthreads();

    float sn, cs;
    __sincosf(TWO_PI * (float)(k1 * t) * INV_N, &sn, &cs);
    float2 base = make_float2(cs, sn);
    __sincosf(TWO_PI * (float)k1 * (1.0f / 8192.0f), &sn, &cs);
    float2 A = make_float2(cs, sn);
    __sincosf(TWO_PI * (float)k1 * (1.0f / 2048.0f), &sn, &cs);
    float2 Bm = make_float2(cs, sn);
    float2 ob[4];
    ob[0] = base;
    ob[1] = cmul(base, A);
    ob[2] = cmul(ob[1], A);
    ob[3] = cmul(ob[2], A);
#pragma unroll
    for (int i = 0; i < 4; i++) {
        float2 a = h2f(S[PD(t + 64 * i)]);
        float2 b = h2f(S[PD(t + 64 * i + 256)]);
        float2 c = h2f(S[PD(t + 64 * i + 512)]);
        float2 d = h2f(S[PD(t + 64 * i + 768)]);
        fft4i<1>(a, b, c, d);
        float2 w = ob[i];
        rout[t + 64 * i]       = f2h(cmul(a, w)); w = cmul(w, Bm);
        rout[t + 64 * i + 256] = f2h(cmul(b, w)); w = cmul(w, Bm);
        rout[t + 64 * i + 512] = f2h(cmul(c, w)); w = cmul(w, Bm);
        rout[t + 64 * i + 768] = f2h(cmul(d, w));
    }
}

// ---------------- Pass C: column iFFT-512 (fp16 smem) + add identity (x) + scatter --------
__global__ void __launch_bounds__(512, 2) passC(float* __restrict__ dout,
                                                const float* __restrict__ x) {
    extern __shared__ __align__(16) char smraw[];
    __half2* sb = (__half2*)smraw;
    int sig = blockIdx.x >> 6;
    int cb  = (blockIdx.x & 63) << 4;
    int pair = sig / NFRAME;
    int f    = sig - pair * NFRAME;
    const __half2* in = g_B + (size_t)sig * FFT_N;

    int c = threadIdx.x & 15, r = threadIdx.x >> 4;
    int n2 = cb + c;
    float2 v[16];
#pragma unroll
    for (int m = 0; m < 16; m++) v[m] = h2f(__ldg(in + (r + 32 * m) * N2 + n2));
    col_fft512<1, __half2>(v, sb, c, r);

    int b0 = 2 * pair;
    const float* x0 = x + (size_t)b0 * LX;
    const float* x1 = x0 + LX;
    float* o0 = dout + (size_t)b0 * LX;
    float* o1 = o0 + LX;
#pragma unroll
    for (int m = 0; m < 16; m++) {
        int n1 = r + 32 * m;
        int tt = n1 * N2 + n2 - (KLEN - 1);
        if (tt >= 0) {
            int no = f * VALID + tt;
            if (no < LX) {
                o0[no] = fmaf(v[m].x, INV_TS, __ldg(x0 + no));
                o1[no] = fmaf(v[m].y, INV_TS, __ldg(x1 + no));
            }
        }
    }
}

extern "C" void kernel_launch(void* const* d_in, const int* in_sizes, int n_in,
                              void* d_out, int out_size) {
    (void)in_sizes; (void)n_in; (void)out_size;
    const float* x   = (const float*)d_in[0];
    const float* irp = (const float*)d_in[1];
    float* out = (float*)d_out;

    cudaFuncSetAttribute(passA_fused, cudaFuncAttributeMaxDynamicSharedMemorySize, CSMEM_B_F32);

    passA_fused<<<A_MAIN_BLOCKS + A_H_BLOCKS, 512, CSMEM_B_F32>>>(x, irp);  // 1600 blocks
    passB_H<<<N1, 128>>>();                                                  // 512 blocks
    passB_main<<<NSIG * N1 / 2, 128>>>();                                    // 6144 blocks
    passC<<<NSIG * (N2 / 16), 512, CSMEM_B_F16>>>(out, x);                   // 1536 blocks
}